// round 1
// baseline (speedup 1.0000x reference)
#include <cuda_runtime.h>
#include <cuda_bf16.h>

#define IN_DIM   32
#define HARM     5
#define NBASIS   11          // 2*HARM + 1
#define HIDDEN   64
#define BLOCK    256
#define HALF_H   32          // outputs per thread (2 threads per row)
#define ROWS_PER_BLOCK (BLOCK / 2)

#define W_FLOATS (IN_DIM * NBASIS * HIDDEN)   // 22528 floats = 88 KB
#define SMEM_BYTES ((W_FLOATS + HIDDEN) * sizeof(float))

__global__ void __launch_bounds__(BLOCK, 2)
kan_kernel(const float* __restrict__ x,
           const float* __restrict__ W,
           const float* __restrict__ b,
           float* __restrict__ out,
           int n_rows)
{
    extern __shared__ float sm[];
    float* Wsm  = sm;                 // [f][c][h] contiguous, 22528 floats
    float* bsum = sm + W_FLOATS;      // [64]

    const int tid = threadIdx.x;

    // ---- stage W into SMEM (coalesced float4) ----
    {
        const float4* Wg  = (const float4*)W;
        float4*       Ws4 = (float4*)Wsm;
        #pragma unroll
        for (int i = tid; i < W_FLOATS / 4; i += BLOCK)
            Ws4[i] = Wg[i];
    }
    // ---- summed bias (tiny, redundant per block) ----
    if (tid < HIDDEN) {
        float s = 0.f;
        #pragma unroll
        for (int f = 0; f < IN_DIM; f++)
            s += b[f * HIDDEN + tid];
        bsum[tid] = s;
    }
    __syncthreads();

    const int row   = blockIdx.x * ROWS_PER_BLOCK + (tid >> 1);
    const int hbase = (tid & 1) * HALF_H;
    if (row >= n_rows) return;

    float acc[HALF_H];
    #pragma unroll
    for (int h = 0; h < HALF_H; h++)
        acc[h] = bsum[hbase + h];

    const float* xrow = x + row * IN_DIM;

    // ---- main contraction: 32 features x 11 basis x 32 outputs ----
    #pragma unroll 1
    for (int f = 0; f < IN_DIM; f++) {
        const float xval = __ldg(xrow + f);

        float s1, c1;
        __sincosf(xval, &s1, &c1);

        // basis = [1, sin1, cos1, sin2, cos2, ... sin5, cos5] via recurrence
        float bas[NBASIS];
        bas[0] = 1.f;
        bas[1] = s1;
        bas[2] = c1;
        float sk = s1, ck = c1;
        #pragma unroll
        for (int k = 1; k < HARM; k++) {
            float sn = sk * c1 + ck * s1;
            float cn = ck * c1 - sk * s1;
            bas[2 * k + 1] = sn;
            bas[2 * k + 2] = cn;
            sk = sn; ck = cn;
        }

        const float* wf = Wsm + f * (NBASIS * HIDDEN) + hbase;
        #pragma unroll
        for (int c = 0; c < NBASIS; c++) {
            const float4* wc = (const float4*)(wf + c * HIDDEN);
            const float bv = bas[c];
            #pragma unroll
            for (int j = 0; j < HALF_H / 4; j++) {
                float4 w4 = wc[j];
                acc[4 * j + 0] += bv * w4.x;
                acc[4 * j + 1] += bv * w4.y;
                acc[4 * j + 2] += bv * w4.z;
                acc[4 * j + 3] += bv * w4.w;
            }
        }
    }

    // ---- store 32 outputs as 8x float4 ----
    float4* og = (float4*)(out + row * HIDDEN + hbase);
    #pragma unroll
    for (int j = 0; j < HALF_H / 4; j++)
        og[j] = make_float4(acc[4 * j + 0], acc[4 * j + 1],
                            acc[4 * j + 2], acc[4 * j + 3]);
}

extern "C" void kernel_launch(void* const* d_in, const int* in_sizes, int n_in,
                              void* d_out, int out_size)
{
    const float* x = (const float*)d_in[0];
    const float* W = (const float*)d_in[1];
    const float* b = (const float*)d_in[2];
    float* out = (float*)d_out;

    const int n_rows = in_sizes[0] / IN_DIM;   // 131072

    cudaFuncSetAttribute(kan_kernel,
                         cudaFuncAttributeMaxDynamicSharedMemorySize,
                         (int)SMEM_BYTES);

    const int blocks = (n_rows + ROWS_PER_BLOCK - 1) / ROWS_PER_BLOCK;
    kan_kernel<<<blocks, BLOCK, SMEM_BYTES>>>(x, W, b, out, n_rows);
}

// round 3
// speedup vs baseline: 2.6799x; 2.6799x over previous
#include <cuda_runtime.h>
#include <cuda_bf16.h>

#define IN_DIM   32
#define HARM     5
#define NBASIS   11          // 2*HARM + 1
#define HIDDEN   64
#define BLOCK    128
#define TPR      4           // threads per row (h split)
#define R        4           // rows per thread
#define ROWS_PER_CTA ((BLOCK / TPR) * R)   // 128

#define W_FLOATS (IN_DIM * NBASIS * HIDDEN)   // 22528 floats = 88 KB
#define SMEM_BYTES ((W_FLOATS + HIDDEN) * sizeof(float))

typedef unsigned long long u64;

__device__ __forceinline__ u64 pack2(float a, float b) {
    u64 r;
    asm("mov.b64 %0, {%1, %2};" : "=l"(r) : "f"(a), "f"(b));
    return r;
}

__device__ __forceinline__ u64 fma2(u64 a, u64 b, u64 c) {
    u64 d;
    asm("fma.rn.f32x2 %0, %1, %2, %3;" : "=l"(d) : "l"(a), "l"(b), "l"(c));
    return d;
}

__global__ void __launch_bounds__(BLOCK, 2)
kan_kernel(const float* __restrict__ x,
           const float* __restrict__ W,
           const float* __restrict__ b,
           float* __restrict__ out,
           int n_rows)
{
    extern __shared__ float sm[];
    float* Wsm  = sm;                 // [f][c][h], 22528 floats
    float* bsum = sm + W_FLOATS;      // [64]

    const int tid = threadIdx.x;

    // ---- stage W into SMEM (coalesced float4) ----
    {
        const float4* Wg  = (const float4*)W;
        float4*       Ws4 = (float4*)Wsm;
        #pragma unroll
        for (int i = tid; i < W_FLOATS / 4; i += BLOCK)
            Ws4[i] = Wg[i];
    }
    if (tid < HIDDEN) {
        float s = 0.f;
        #pragma unroll
        for (int f = 0; f < IN_DIM; f++)
            s += b[f * HIDDEN + tid];
        bsum[tid] = s;
    }
    __syncthreads();

    const int g    = tid >> 2;        // row-group within CTA (0..31)
    const int ht   = tid & 3;         // h-thread: owns h = ht*4 + 16j, j=0..3
    const int row0 = blockIdx.x * ROWS_PER_CTA + g * R;
    if (row0 >= n_rows) return;

    // accumulators: [row r][j][pair p] -> packed (h, h+1) fp32 pairs
    u64 acc[R][4][2];
    #pragma unroll
    for (int j = 0; j < 4; j++) {
        const int h = ht * 4 + 16 * j;
        u64 p0 = pack2(bsum[h + 0], bsum[h + 1]);
        u64 p1 = pack2(bsum[h + 2], bsum[h + 3]);
        #pragma unroll
        for (int r = 0; r < R; r++) { acc[r][j][0] = p0; acc[r][j][1] = p1; }
    }

    const float* xr = x + (long)row0 * IN_DIM;

    #pragma unroll 1
    for (int f = 0; f < IN_DIM; f++) {
        // ---- basis for R rows ----
        float bas[R][NBASIS];
        #pragma unroll
        for (int r = 0; r < R; r++) {
            const float xv = __ldg(xr + r * IN_DIM + f);
            float s1, c1;
            __sincosf(xv, &s1, &c1);
            bas[r][0] = 1.f;
            bas[r][1] = s1;
            bas[r][2] = c1;
            float sk = s1, ck = c1;
            #pragma unroll
            for (int k = 1; k < HARM; k++) {
                float sn = sk * c1 + ck * s1;
                float cn = ck * c1 - sk * s1;
                bas[r][2 * k + 1] = sn;
                bas[r][2 * k + 2] = cn;
                sk = sn; ck = cn;
            }
        }

        const float* wf = Wsm + f * (NBASIS * HIDDEN) + ht * 4;
        #pragma unroll
        for (int c = 0; c < NBASIS; c++) {
            // 4 conflict-free LDS.128: lanes ht=0..3 cover 64B contiguous.
            // ulonglong2 = 4 floats, so +16 floats = index 4.
            const ulonglong2* wc = (const ulonglong2*)(wf + c * HIDDEN);
            ulonglong2 w0 = wc[0];    // h offsets ht*4 + 0..3
            ulonglong2 w1 = wc[4];    // +16
            ulonglong2 w2 = wc[8];    // +32
            ulonglong2 w3 = wc[12];   // +48

            #pragma unroll
            for (int r = 0; r < R; r++) {
                const u64 bb = pack2(bas[r][c], bas[r][c]);
                acc[r][0][0] = fma2(w0.x, bb, acc[r][0][0]);
                acc[r][0][1] = fma2(w0.y, bb, acc[r][0][1]);
                acc[r][1][0] = fma2(w1.x, bb, acc[r][1][0]);
                acc[r][1][1] = fma2(w1.y, bb, acc[r][1][1]);
                acc[r][2][0] = fma2(w2.x, bb, acc[r][2][0]);
                acc[r][2][1] = fma2(w2.y, bb, acc[r][2][1]);
                acc[r][3][0] = fma2(w3.x, bb, acc[r][3][0]);
                acc[r][3][1] = fma2(w3.y, bb, acc[r][3][1]);
            }
        }
    }

    // ---- stores: 4 rows x 4 float4 (16B-aligned) ----
    #pragma unroll
    for (int r = 0; r < R; r++) {
        float* orow = out + (long)(row0 + r) * HIDDEN + ht * 4;
        #pragma unroll
        for (int j = 0; j < 4; j++) {
            ulonglong2 v;
            v.x = acc[r][j][0];
            v.y = acc[r][j][1];
            *(ulonglong2*)(orow + 16 * j) = v;
        }
    }
}

extern "C" void kernel_launch(void* const* d_in, const int* in_sizes, int n_in,
                              void* d_out, int out_size)
{
    const float* x = (const float*)d_in[0];
    const float* W = (const float*)d_in[1];
    const float* b = (const float*)d_in[2];
    float* out = (float*)d_out;

    const int n_rows = in_sizes[0] / IN_DIM;   // 131072

    cudaFuncSetAttribute(kan_kernel,
                         cudaFuncAttributeMaxDynamicSharedMemorySize,
                         (int)SMEM_BYTES);

    const int blocks = (n_rows + ROWS_PER_CTA - 1) / ROWS_PER_CTA;
    kan_kernel<<<blocks, BLOCK, SMEM_BYTES>>>(x, W, b, out, n_rows);
}

// round 5
// speedup vs baseline: 3.8412x; 1.4333x over previous
#include <cuda_runtime.h>
#include <cuda_bf16.h>
#include <cstdint>

#define IN_DIM   32
#define NB       11
#define FPAD     12                    // padded basis cols per feature
#define HID      64
#define KTOT     (IN_DIM * FPAD)       // 384
#define TILE_M   128
#define NCHUNK   4
#define FPC      8                     // features per chunk
#define KSTEPS   6                     // k16-steps per chunk (96 cols)
#define KS_TOTAL 24
#define THREADS  256

#define A_STRIDE    104                // bf16 cols per row incl pad (conflict-free)
#define A_STRIDE_B  (A_STRIDE * 2)     // 208 bytes

// ---- SMEM layout (bytes) ----
#define AH_OFF   0
#define AL_OFF   (TILE_M * A_STRIDE_B)            // 26624
#define BH_OFF   (2 * TILE_M * A_STRIDE_B)        // 53248
#define BFRAG_BYTES (KS_TOTAL * 8 * 32 * 8)       // 49152
#define BL_OFF   (BH_OFF + BFRAG_BYTES)           // 102400
#define BSUM_OFF (BL_OFF + BFRAG_BYTES)           // 151552
#define SMEM_TOTAL (BSUM_OFF + 256)

__device__ __align__(16) unsigned char g_Bh[BFRAG_BYTES];
__device__ __align__(16) unsigned char g_Bl[BFRAG_BYTES];

// ---------------------------------------------------------------- helpers
__device__ __forceinline__ uint32_t smem_u32(const void* p) {
    uint32_t a;
    asm("{ .reg .u64 t; cvta.to.shared.u64 t, %1; cvt.u32.u64 %0, t; }"
        : "=r"(a) : "l"(p));
    return a;
}
// pack (v0 -> low bf16, v1 -> high bf16), return residuals
__device__ __forceinline__ uint32_t pack_hi(float v0, float v1, float& l0, float& l1) {
    uint32_t d;
    asm("cvt.rn.bf16x2.f32 %0, %1, %2;" : "=r"(d) : "f"(v1), "f"(v0));
    l0 = v0 - __uint_as_float(d << 16);
    l1 = v1 - __uint_as_float(d & 0xFFFF0000u);
    return d;
}
__device__ __forceinline__ uint32_t pack_only(float v0, float v1) {
    uint32_t d;
    asm("cvt.rn.bf16x2.f32 %0, %1, %2;" : "=r"(d) : "f"(v1), "f"(v0));
    return d;
}
__device__ __forceinline__ void ldm4(uint32_t* r, uint32_t a) {
    asm volatile("ldmatrix.sync.aligned.m8n8.x4.shared.b16 {%0,%1,%2,%3}, [%4];"
                 : "=r"(r[0]), "=r"(r[1]), "=r"(r[2]), "=r"(r[3]) : "r"(a));
}
__device__ __forceinline__ void lds64(uint32_t* r, uint32_t a) {
    asm volatile("ld.shared.v2.b32 {%0,%1}, [%2];"
                 : "=r"(r[0]), "=r"(r[1]) : "r"(a));
}
__device__ __forceinline__ void sts32(uint32_t a, uint32_t v) {
    asm volatile("st.shared.b32 [%0], %1;" :: "r"(a), "r"(v) : "memory");
}
__device__ __forceinline__ void mma16816(float* d, const uint32_t* a, const uint32_t* b) {
    asm volatile(
        "mma.sync.aligned.m16n8k16.row.col.f32.bf16.bf16.f32 "
        "{%0,%1,%2,%3}, {%4,%5,%6,%7}, {%8,%9}, {%0,%1,%2,%3};"
        : "+f"(d[0]), "+f"(d[1]), "+f"(d[2]), "+f"(d[3])
        : "r"(a[0]), "r"(a[1]), "r"(a[2]), "r"(a[3]), "r"(b[0]), "r"(b[1]));
}

// ---------------------------------------------------------------- prep kernel
// Writes W (hi/lo bf16) directly in mma B-fragment layout.
// Logical B[k][n], k = f*12 + c : c<11 -> W[f][c][n], c==11 -> 0.
// Fragment (ksg, nt): thread t owns B[k0+2*(t%4)+{0,1}(+8)][nt*8 + t/4].
__global__ void prep_kernel(const float* __restrict__ W) {
    int idx = blockIdx.x * blockDim.x + threadIdx.x;   // KS_TOTAL*8*32 = 6144
    if (idx >= KS_TOTAL * 8 * 32) return;
    int t   = idx & 31;
    int nt  = (idx >> 5) & 7;
    int ksg = idx >> 8;
    int n     = nt * 8 + (t >> 2);
    int kbase = ksg * 16 + (t & 3) * 2;

    uint32_t hi[2], lo[2];
    #pragma unroll
    for (int half = 0; half < 2; half++) {
        uint32_t hr = 0, lr = 0;
        #pragma unroll
        for (int i = 0; i < 2; i++) {
            int k = kbase + half * 8 + i;
            int f = k / FPAD, c = k % FPAD;
            float v = (c < NB) ? W[(f * NB + c) * HID + n] : 0.f;
            __nv_bfloat16 hb = __float2bfloat16(v);
            float res = v - __bfloat162float(hb);
            __nv_bfloat16 lb = __float2bfloat16(res);
            hr |= ((uint32_t)__bfloat16_as_ushort(hb)) << (16 * i);
            lr |= ((uint32_t)__bfloat16_as_ushort(lb)) << (16 * i);
        }
        hi[half] = hr; lo[half] = lr;
    }
    int off = idx * 8;
    *(uint2*)(g_Bh + off) = make_uint2(hi[0], hi[1]);
    *(uint2*)(g_Bl + off) = make_uint2(lo[0], lo[1]);
}

// ---------------------------------------------------------------- main kernel
__global__ void __launch_bounds__(THREADS, 1)
kan_mma_kernel(const float* __restrict__ x, const float* __restrict__ b,
               float* __restrict__ out, int n_rows)
{
    extern __shared__ __align__(16) unsigned char smem[];
    const uint32_t sbase = smem_u32(smem);
    const int tid  = threadIdx.x;
    const int lane = tid & 31;
    const int wid  = tid >> 5;
    const int mw   = wid & 3;    // M warp: rows mw*32
    const int nw   = wid >> 2;   // N warp: cols nw*32

    // ---- stage B fragments + summed bias ----
    {
        const uint4* sh = (const uint4*)g_Bh;
        const uint4* sl = (const uint4*)g_Bl;
        uint4* dh = (uint4*)(smem + BH_OFF);
        uint4* dl = (uint4*)(smem + BL_OFF);
        #pragma unroll 4
        for (int i = tid; i < BFRAG_BYTES / 16; i += THREADS) { dh[i] = sh[i]; dl[i] = sl[i]; }
    }
    if (tid < HID) {
        float s = 0.f;
        #pragma unroll
        for (int f = 0; f < IN_DIM; f++) s += b[f * HID + tid];
        ((float*)(smem + BSUM_OFF))[tid] = s;
    }

    const long tile_row0 = (long)blockIdx.x * TILE_M;

    float d[2][4][4];
    #pragma unroll
    for (int mt = 0; mt < 2; mt++)
        #pragma unroll
        for (int j = 0; j < 4; j++)
            #pragma unroll
            for (int e = 0; e < 4; e++) d[mt][j][e] = 0.f;

    // ldmatrix per-lane base address (A hi)
    const int lrow = lane & 15, lcol = lane >> 4;
    const uint32_t aBase = sbase + AH_OFF + (mw * 32 + lrow) * A_STRIDE_B + lcol * 16;

    __syncthreads();   // B + bsum ready; also fences before first A gen reuse

    for (int ch = 0; ch < NCHUNK; ch++) {
        // === generate A chunk: 128 rows x 8 features, hi/lo bf16 ===
        #pragma unroll
        for (int i = 0; i < 4; i++) {
            const int job = tid + THREADS * i;     // 0..1023
            const int r   = job >> 3;
            const int fl  = job & 7;
            const long grow = tile_row0 + r;
            const int f = ch * FPC + fl;
            float xv = (grow < n_rows) ? __ldg(x + grow * IN_DIM + f) : 0.f;

            // range reduce by pi, Taylor sin/cos
            float t  = fmaf(xv, 0.3183098861837907f, 12582912.0f);
            uint32_t ti = __float_as_uint(t);
            float nf = t - 12582912.0f;
            float rr = fmaf(nf, -3.14159274101257324f, xv);
            rr = fmaf(nf, 8.74227800037247e-8f, rr);
            float sgn = (ti & 1u) ? -1.0f : 1.0f;

            float r2 = rr * rr;
            float sp = -2.50521083854e-8f;
            sp = fmaf(sp, r2, 2.75573192240e-6f);
            sp = fmaf(sp, r2, -1.98412698413e-4f);
            sp = fmaf(sp, r2, 8.33333333333e-3f);
            sp = fmaf(sp, r2, -1.66666666667e-1f);
            float s1 = fmaf(sp * r2, rr, rr);
            float cp = 2.08767569879e-9f;
            cp = fmaf(cp, r2, -2.75573192240e-7f);
            cp = fmaf(cp, r2, 2.48015873016e-5f);
            cp = fmaf(cp, r2, -1.38888888889e-3f);
            cp = fmaf(cp, r2, 4.16666666667e-2f);
            cp = fmaf(cp, r2, -0.5f);
            float c1 = fmaf(cp, r2, 1.0f);
            s1 *= sgn; c1 *= sgn;

            float s2 = 2.f * s1 * c1;
            float c2 = fmaf(c1, c1, -(s1 * s1));
            float s3 = s2 * c1 + c2 * s1;
            float c3 = c2 * c1 - s2 * s1;
            float s4 = s3 * c1 + c3 * s1;
            float c4 = c3 * c1 - s3 * s1;
            float s5 = s4 * c1 + c4 * s1;
            float c5 = c4 * c1 - s4 * s1;

            float v[12] = {1.f, s1, c1, s2, c2, s3, c3, s4, c4, s5, c5, 0.f};
            const uint32_t wb = sbase + r * A_STRIDE_B + fl * 24;
            #pragma unroll
            for (int p = 0; p < 6; p++) {
                float l0, l1;
                uint32_t hp = pack_hi(v[2 * p], v[2 * p + 1], l0, l1);
                uint32_t lp = pack_only(l0, l1);
                sts32(wb + AH_OFF + p * 4, hp);
                sts32(wb + AL_OFF + p * 4, lp);
            }
        }
        __syncthreads();

        // === mma: 6 k-steps x 3 precision terms x (2 m-tiles x 4 n-tiles) ===
        #pragma unroll
        for (int s = 0; s < KSTEPS; s++) {
            uint32_t aAddr = aBase + s * 32;
            uint32_t ah[2][4], al[2][4];
            ldm4(ah[0], aAddr);
            ldm4(ah[1], aAddr + 16 * A_STRIDE_B);
            ldm4(al[0], aAddr + (AL_OFF - AH_OFF));
            ldm4(al[1], aAddr + (AL_OFF - AH_OFF) + 16 * A_STRIDE_B);

            uint32_t bh[4][2], bl[4][2];
            const int fragIdx = ((ch * KSTEPS + s) * 8 + nw * 4);
            #pragma unroll
            for (int j = 0; j < 4; j++) {
                uint32_t ba = sbase + BH_OFF + (fragIdx + j) * 256 + lane * 8;
                lds64(bh[j], ba);
                lds64(bl[j], ba + BFRAG_BYTES);
            }

            #pragma unroll
            for (int mt = 0; mt < 2; mt++)
                #pragma unroll
                for (int j = 0; j < 4; j++) {
                    mma16816(d[mt][j], ah[mt], bh[j]);   // hi*hi
                    mma16816(d[mt][j], al[mt], bh[j]);   // lo*hi
                    mma16816(d[mt][j], ah[mt], bl[j]);   // hi*lo
                }
        }
        __syncthreads();
    }

    // ---- epilogue: add summed bias, store ----
    const float* bs = (const float*)(smem + BSUM_OFF);
    #pragma unroll
    for (int mt = 0; mt < 2; mt++) {
        #pragma unroll
        for (int half = 0; half < 2; half++) {
            const long grow = tile_row0 + mw * 32 + mt * 16 + (lane >> 2) + half * 8;
            if (grow < n_rows) {
                #pragma unroll
                for (int j = 0; j < 4; j++) {
                    const int col = nw * 32 + j * 8 + (lane & 3) * 2;
                    float2 v;
                    v.x = d[mt][j][half * 2 + 0] + bs[col];
                    v.y = d[mt][j][half * 2 + 1] + bs[col + 1];
                    *(float2*)(out + grow * HID + col) = v;
                }
            }
        }
    }
}

// ---------------------------------------------------------------- launch
extern "C" void kernel_launch(void* const* d_in, const int* in_sizes, int n_in,
                              void* d_out, int out_size)
{
    const float* x = (const float*)d_in[0];
    const float* W = (const float*)d_in[1];
    const float* b = (const float*)d_in[2];
    float* out = (float*)d_out;

    const int n_rows = in_sizes[0] / IN_DIM;    // 131072
    const int tiles = (n_rows + TILE_M - 1) / TILE_M;

    cudaFuncSetAttribute(kan_mma_kernel,
                         cudaFuncAttributeMaxDynamicSharedMemorySize, SMEM_TOTAL);

    prep_kernel<<<(KS_TOTAL * 8 * 32 + 255) / 256, 256>>>(W);
    kan_mma_kernel<<<tiles, THREADS, SMEM_TOTAL>>>(x, b, out, n_rows);
}

// round 6
// speedup vs baseline: 4.5701x; 1.1898x over previous
#include <cuda_runtime.h>
#include <cuda_bf16.h>
#include <cstdint>

#define IN_DIM   32
#define NB       11
#define FPAD     12                    // padded basis cols per feature (col 11 = bias)
#define HID      64
#define TILE_M   128
#define NCHUNK   4
#define FPC      8                     // features per chunk
#define KSTEPS   6                     // k16-steps per chunk (96 cols)
#define KS_TOTAL 24
#define THREADS  256

#define A_STRIDE    104                // bf16 cols per row incl pad (conflict-free ldmatrix)
#define A_STRIDE_B  (A_STRIDE * 2)     // 208 bytes

// ---- SMEM layout (bytes): A tiles only ----
#define AH_OFF   0
#define AL_OFF   (TILE_M * A_STRIDE_B)            // 26624
#define SMEM_TOTAL (2 * TILE_M * A_STRIDE_B)      // 53248

#define BFRAG_BYTES (KS_TOTAL * 8 * 32 * 8)       // 49152

__device__ __align__(16) unsigned char g_Bh[BFRAG_BYTES];
__device__ __align__(16) unsigned char g_Bl[BFRAG_BYTES];

// ---------------------------------------------------------------- helpers
__device__ __forceinline__ uint32_t smem_u32(const void* p) {
    uint32_t a;
    asm("{ .reg .u64 t; cvta.to.shared.u64 t, %1; cvt.u32.u64 %0, t; }"
        : "=r"(a) : "l"(p));
    return a;
}
__device__ __forceinline__ uint32_t pack_hi(float v0, float v1, float& l0, float& l1) {
    uint32_t d;
    asm("cvt.rn.bf16x2.f32 %0, %1, %2;" : "=r"(d) : "f"(v1), "f"(v0));
    l0 = v0 - __uint_as_float(d << 16);
    l1 = v1 - __uint_as_float(d & 0xFFFF0000u);
    return d;
}
__device__ __forceinline__ uint32_t pack_only(float v0, float v1) {
    uint32_t d;
    asm("cvt.rn.bf16x2.f32 %0, %1, %2;" : "=r"(d) : "f"(v1), "f"(v0));
    return d;
}
__device__ __forceinline__ void ldm4(uint32_t* r, uint32_t a) {
    asm volatile("ldmatrix.sync.aligned.m8n8.x4.shared.b16 {%0,%1,%2,%3}, [%4];"
                 : "=r"(r[0]), "=r"(r[1]), "=r"(r[2]), "=r"(r[3]) : "r"(a));
}
__device__ __forceinline__ void sts32(uint32_t a, uint32_t v) {
    asm volatile("st.shared.b32 [%0], %1;" :: "r"(a), "r"(v) : "memory");
}
__device__ __forceinline__ void mma16816(float* d, const uint32_t* a, const uint32_t* b) {
    asm volatile(
        "mma.sync.aligned.m16n8k16.row.col.f32.bf16.bf16.f32 "
        "{%0,%1,%2,%3}, {%4,%5,%6,%7}, {%8,%9}, {%0,%1,%2,%3};"
        : "+f"(d[0]), "+f"(d[1]), "+f"(d[2]), "+f"(d[3])
        : "r"(a[0]), "r"(a[1]), "r"(a[2]), "r"(a[3]), "r"(b[0]), "r"(b[1]));
}

// ---------------------------------------------------------------- prep kernel
// Writes W+bias (hi/lo bf16) directly in mma B-fragment layout.
// Logical B[k][n], k = f*12 + c : c<11 -> W[f][c][n], c==11 -> b[f][n].
__global__ void prep_kernel(const float* __restrict__ W, const float* __restrict__ bias) {
    int idx = blockIdx.x * blockDim.x + threadIdx.x;   // KS_TOTAL*8*32 = 6144
    if (idx >= KS_TOTAL * 8 * 32) return;
    int t   = idx & 31;
    int nt  = (idx >> 5) & 7;
    int ksg = idx >> 8;
    int n     = nt * 8 + (t >> 2);
    int kbase = ksg * 16 + (t & 3) * 2;

    uint32_t hi[2], lo[2];
    #pragma unroll
    for (int half = 0; half < 2; half++) {
        uint32_t hr = 0, lr = 0;
        #pragma unroll
        for (int i = 0; i < 2; i++) {
            int k = kbase + half * 8 + i;
            int f = k / FPAD, c = k % FPAD;
            float v = (c < NB) ? W[(f * NB + c) * HID + n] : bias[f * HID + n];
            __nv_bfloat16 hb = __float2bfloat16(v);
            float res = v - __bfloat162float(hb);
            __nv_bfloat16 lb = __float2bfloat16(res);
            hr |= ((uint32_t)__bfloat16_as_ushort(hb)) << (16 * i);
            lr |= ((uint32_t)__bfloat16_as_ushort(lb)) << (16 * i);
        }
        hi[half] = hr; lo[half] = lr;
    }
    int off = idx * 8;
    *(uint2*)(g_Bh + off) = make_uint2(hi[0], hi[1]);
    *(uint2*)(g_Bl + off) = make_uint2(lo[0], lo[1]);
}

// ---------------------------------------------------------------- main kernel
__global__ void __launch_bounds__(THREADS, 2)
kan_mma_kernel(const float* __restrict__ x, float* __restrict__ out, int n_rows)
{
    extern __shared__ __align__(16) unsigned char smem[];
    const uint32_t sbase = smem_u32(smem);
    const int tid  = threadIdx.x;
    const int lane = tid & 31;
    const int wid  = tid >> 5;
    const int mw   = wid & 3;    // M warp: rows mw*32
    const int nw   = wid >> 2;   // N warp: cols nw*32

    const long tile_row0 = (long)blockIdx.x * TILE_M;

    float d[2][4][4];
    #pragma unroll
    for (int mt = 0; mt < 2; mt++)
        #pragma unroll
        for (int j = 0; j < 4; j++)
            #pragma unroll
            for (int e = 0; e < 4; e++) d[mt][j][e] = 0.f;

    const int lrow = lane & 15, lcol = lane >> 4;
    const uint32_t aBase = sbase + AH_OFF + (mw * 32 + lrow) * A_STRIDE_B + lcol * 16;

    for (int ch = 0; ch < NCHUNK; ch++) {
        // === generate A chunk: 128 rows x 8 features, hi/lo bf16 ===
        #pragma unroll
        for (int i = 0; i < 4; i++) {
            const int job = tid + THREADS * i;     // 0..1023
            const int r   = job >> 3;
            const int fl  = job & 7;
            const long grow = tile_row0 + r;
            const int f = ch * FPC + fl;
            float xv = (grow < n_rows) ? __ldg(x + grow * IN_DIM + f) : 0.f;

            // range reduce by pi, Taylor sin/cos (FMA-only, no MUFU)
            float t  = fmaf(xv, 0.3183098861837907f, 12582912.0f);
            uint32_t ti = __float_as_uint(t);
            float nf = t - 12582912.0f;
            float rr = fmaf(nf, -3.14159274101257324f, xv);
            rr = fmaf(nf, 8.74227800037247e-8f, rr);
            float sgn = (ti & 1u) ? -1.0f : 1.0f;

            float r2 = rr * rr;
            float sp = -2.50521083854e-8f;
            sp = fmaf(sp, r2, 2.75573192240e-6f);
            sp = fmaf(sp, r2, -1.98412698413e-4f);
            sp = fmaf(sp, r2, 8.33333333333e-3f);
            sp = fmaf(sp, r2, -1.66666666667e-1f);
            float s1 = fmaf(sp * r2, rr, rr);
            float cp = 2.08767569879e-9f;
            cp = fmaf(cp, r2, -2.75573192240e-7f);
            cp = fmaf(cp, r2, 2.48015873016e-5f);
            cp = fmaf(cp, r2, -1.38888888889e-3f);
            cp = fmaf(cp, r2, 4.16666666667e-2f);
            cp = fmaf(cp, r2, -0.5f);
            float c1 = fmaf(cp, r2, 1.0f);
            s1 *= sgn; c1 *= sgn;

            float s2 = 2.f * s1 * c1;
            float c2 = fmaf(c1, c1, -(s1 * s1));
            float s3 = s2 * c1 + c2 * s1;
            float c3 = c2 * c1 - s2 * s1;
            float s4 = s3 * c1 + c3 * s1;
            float c4 = c3 * c1 - s3 * s1;
            float s5 = s4 * c1 + c4 * s1;
            float c5 = c4 * c1 - s4 * s1;

            // col 11 = 1.0 -> bias column of B contributes sum_f b[f][:]
            float v[12] = {1.f, s1, c1, s2, c2, s3, c3, s4, c4, s5, c5, 1.f};
            const uint32_t wb = sbase + r * A_STRIDE_B + fl * 24;
            #pragma unroll
            for (int p = 0; p < 6; p++) {
                float l0, l1;
                uint32_t hp = pack_hi(v[2 * p], v[2 * p + 1], l0, l1);
                uint32_t lp = pack_only(l0, l1);
                sts32(wb + AH_OFF + p * 4, hp);
                sts32(wb + AL_OFF + p * 4, lp);
            }
        }
        __syncthreads();

        // === mma: 6 k-steps x 3 precision terms x (2 m-tiles x 4 n-tiles) ===
        #pragma unroll
        for (int s = 0; s < KSTEPS; s++) {
            uint32_t aAddr = aBase + s * 32;
            uint32_t ah[2][4], al[2][4];
            ldm4(ah[0], aAddr);
            ldm4(ah[1], aAddr + 16 * A_STRIDE_B);
            ldm4(al[0], aAddr + (AL_OFF - AH_OFF));
            ldm4(al[1], aAddr + (AL_OFF - AH_OFF) + 16 * A_STRIDE_B);

            // B fragments straight from global (L1/L2-resident, shared by all CTAs)
            uint32_t bh[4][2], bl[4][2];
            const int fragIdx = ((ch * KSTEPS + s) * 8 + nw * 4);
            #pragma unroll
            for (int j = 0; j < 4; j++) {
                const int off = (fragIdx + j) * 256 + lane * 8;
                uint2 vh = __ldg((const uint2*)(g_Bh + off));
                uint2 vl = __ldg((const uint2*)(g_Bl + off));
                bh[j][0] = vh.x; bh[j][1] = vh.y;
                bl[j][0] = vl.x; bl[j][1] = vl.y;
            }

            #pragma unroll
            for (int mt = 0; mt < 2; mt++)
                #pragma unroll
                for (int j = 0; j < 4; j++) {
                    mma16816(d[mt][j], ah[mt], bh[j]);   // hi*hi
                    mma16816(d[mt][j], al[mt], bh[j]);   // lo*hi
                    mma16816(d[mt][j], ah[mt], bl[j]);   // hi*lo
                }
        }
        __syncthreads();
    }

    // ---- epilogue: store (bias already folded into GEMM) ----
    #pragma unroll
    for (int mt = 0; mt < 2; mt++) {
        #pragma unroll
        for (int half = 0; half < 2; half++) {
            const long grow = tile_row0 + mw * 32 + mt * 16 + (lane >> 2) + half * 8;
            if (grow < n_rows) {
                #pragma unroll
                for (int j = 0; j < 4; j++) {
                    const int col = nw * 32 + j * 8 + (lane & 3) * 2;
                    float2 v;
                    v.x = d[mt][j][half * 2 + 0];
                    v.y = d[mt][j][half * 2 + 1];
                    *(float2*)(out + grow * HID + col) = v;
                }
            }
        }
    }
}

// ---------------------------------------------------------------- launch
extern "C" void kernel_launch(void* const* d_in, const int* in_sizes, int n_in,
                              void* d_out, int out_size)
{
    const float* x = (const float*)d_in[0];
    const float* W = (const float*)d_in[1];
    const float* b = (const float*)d_in[2];
    float* out = (float*)d_out;

    const int n_rows = in_sizes[0] / IN_DIM;    // 131072
    const int tiles = (n_rows + TILE_M - 1) / TILE_M;

    cudaFuncSetAttribute(kan_mma_kernel,
                         cudaFuncAttributeMaxDynamicSharedMemorySize, SMEM_TOTAL);

    prep_kernel<<<(KS_TOTAL * 8 * 32 + 255) / 256, 256>>>(W, b);
    kan_mma_kernel<<<tiles, THREADS, SMEM_TOTAL>>>(x, out, n_rows);
}

// round 7
// speedup vs baseline: 5.8048x; 1.2702x over previous
#include <cuda_runtime.h>
#include <cuda_bf16.h>
#include <cstdint>

#define IN_DIM   32
#define NB       11
#define FPAD     10                    // basis cols per feature in GEMM (sin/cos only)
#define HID      64
#define TILE_M   128
#define NCHUNK   4
#define FPC      8                     // features per chunk
#define KSTEPS   5                     // k16-steps per chunk (80 cols)
#define KS_TOTAL 20
#define THREADS  256

#define A_STRIDE_B  176                // bytes per A row (88 bf16; 80 used) conflict-free

// ---- SMEM layout (bytes): double-buffered A hi/lo ----
#define ABUF_BYTES  (TILE_M * A_STRIDE_B)       // 22528
#define BUF_STRIDE  (2 * ABUF_BYTES)            // 45056 (hi+lo per buffer)
#define SMEM_TOTAL  (2 * BUF_STRIDE)            // 90112

#define BFRAG_BYTES (KS_TOTAL * 8 * 32 * 8)     // 40960

__device__ __align__(16) unsigned char g_Bh[BFRAG_BYTES];
__device__ __align__(16) unsigned char g_Bl[BFRAG_BYTES];
__device__ float g_c0[HID];            // sum_f (W[f][0][:] + b[f][:]), fp32 exact

// ---------------------------------------------------------------- helpers
__device__ __forceinline__ uint32_t smem_u32(const void* p) {
    uint32_t a;
    asm("{ .reg .u64 t; cvta.to.shared.u64 t, %1; cvt.u32.u64 %0, t; }"
        : "=r"(a) : "l"(p));
    return a;
}
__device__ __forceinline__ uint32_t pack_hi(float v0, float v1, float& l0, float& l1) {
    uint32_t d;
    asm("cvt.rn.bf16x2.f32 %0, %1, %2;" : "=r"(d) : "f"(v1), "f"(v0));
    l0 = v0 - __uint_as_float(d << 16);
    l1 = v1 - __uint_as_float(d & 0xFFFF0000u);
    return d;
}
__device__ __forceinline__ uint32_t pack_only(float v0, float v1) {
    uint32_t d;
    asm("cvt.rn.bf16x2.f32 %0, %1, %2;" : "=r"(d) : "f"(v1), "f"(v0));
    return d;
}
__device__ __forceinline__ void ldm4(uint32_t* r, uint32_t a) {
    asm volatile("ldmatrix.sync.aligned.m8n8.x4.shared.b16 {%0,%1,%2,%3}, [%4];"
                 : "=r"(r[0]), "=r"(r[1]), "=r"(r[2]), "=r"(r[3]) : "r"(a));
}
__device__ __forceinline__ void sts32(uint32_t a, uint32_t v) {
    asm volatile("st.shared.b32 [%0], %1;" :: "r"(a), "r"(v) : "memory");
}
__device__ __forceinline__ void mma16816(float* d, const uint32_t* a, const uint32_t* b) {
    asm volatile(
        "mma.sync.aligned.m16n8k16.row.col.f32.bf16.bf16.f32 "
        "{%0,%1,%2,%3}, {%4,%5,%6,%7}, {%8,%9}, {%0,%1,%2,%3};"
        : "+f"(d[0]), "+f"(d[1]), "+f"(d[2]), "+f"(d[3])
        : "r"(a[0]), "r"(a[1]), "r"(a[2]), "r"(a[3]), "r"(b[0]), "r"(b[1]));
}

// ---------------------------------------------------------------- prep kernel
// B[k][n], k = f*10 + c (c=0..9 -> basis col c+1 = sin1,cos1,...,sin5,cos5)
// in mma B-fragment layout, hi/lo bf16 split. Also g_c0 = sum_f(W[f][0]+b[f]).
__global__ void prep_kernel(const float* __restrict__ W, const float* __restrict__ bias) {
    int idx = blockIdx.x * blockDim.x + threadIdx.x;   // KS_TOTAL*8*32 = 5120
    if (idx < HID) {
        float s = 0.f;
        #pragma unroll
        for (int f = 0; f < IN_DIM; f++)
            s += W[(f * NB) * HID + idx] + bias[f * HID + idx];
        g_c0[idx] = s;
    }
    if (idx >= KS_TOTAL * 8 * 32) return;
    int t   = idx & 31;
    int nt  = (idx >> 5) & 7;
    int ksg = idx >> 8;
    int n     = nt * 8 + (t >> 2);
    int kbase = ksg * 16 + (t & 3) * 2;

    uint32_t hi[2], lo[2];
    #pragma unroll
    for (int half = 0; half < 2; half++) {
        uint32_t hr = 0, lr = 0;
        #pragma unroll
        for (int i = 0; i < 2; i++) {
            int k = kbase + half * 8 + i;
            int f = k / FPAD, c = k % FPAD;
            float v = W[(f * NB + c + 1) * HID + n];
            __nv_bfloat16 hb = __float2bfloat16(v);
            float res = v - __bfloat162float(hb);
            __nv_bfloat16 lb = __float2bfloat16(res);
            hr |= ((uint32_t)__bfloat16_as_ushort(hb)) << (16 * i);
            lr |= ((uint32_t)__bfloat16_as_ushort(lb)) << (16 * i);
        }
        hi[half] = hr; lo[half] = lr;
    }
    int off = idx * 8;
    *(uint2*)(g_Bh + off) = make_uint2(hi[0], hi[1]);
    *(uint2*)(g_Bl + off) = make_uint2(lo[0], lo[1]);
}

// ---------------------------------------------------------------- A generation
__device__ __forceinline__ void gen_chunk(const float* __restrict__ x,
                                          unsigned char* smem, uint32_t sbase,
                                          long tile_row0, int n_rows,
                                          int ch, int buf, int tid)
{
    const uint32_t hoff = sbase + buf * BUF_STRIDE;
    #pragma unroll
    for (int i = 0; i < 4; i++) {
        const int job = tid + THREADS * i;     // 0..1023
        const int r   = job >> 3;
        const int fl  = job & 7;
        const long grow = tile_row0 + r;
        const int f = ch * FPC + fl;
        float xv = (grow < n_rows) ? __ldg(x + grow * IN_DIM + f) : 0.f;

        // range reduce by pi, Taylor sin/cos (FMA-only)
        float t  = fmaf(xv, 0.3183098861837907f, 12582912.0f);
        uint32_t ti = __float_as_uint(t);
        float nf = t - 12582912.0f;
        float rr = fmaf(nf, -3.14159274101257324f, xv);
        rr = fmaf(nf, 8.74227800037247e-8f, rr);
        float sgn = (ti & 1u) ? -1.0f : 1.0f;

        float r2 = rr * rr;
        float sp = -2.50521083854e-8f;
        sp = fmaf(sp, r2, 2.75573192240e-6f);
        sp = fmaf(sp, r2, -1.98412698413e-4f);
        sp = fmaf(sp, r2, 8.33333333333e-3f);
        sp = fmaf(sp, r2, -1.66666666667e-1f);
        float s1 = fmaf(sp * r2, rr, rr);
        float cp = 2.08767569879e-9f;
        cp = fmaf(cp, r2, -2.75573192240e-7f);
        cp = fmaf(cp, r2, 2.48015873016e-5f);
        cp = fmaf(cp, r2, -1.38888888889e-3f);
        cp = fmaf(cp, r2, 4.16666666667e-2f);
        cp = fmaf(cp, r2, -0.5f);
        float c1 = fmaf(cp, r2, 1.0f);
        s1 *= sgn; c1 *= sgn;

        float s2 = 2.f * s1 * c1;
        float c2 = fmaf(c1, c1, -(s1 * s1));
        float s3 = s2 * c1 + c2 * s1;
        float c3 = c2 * c1 - s2 * s1;
        float s4 = s3 * c1 + c3 * s1;
        float c4 = c3 * c1 - s3 * s1;
        float s5 = s4 * c1 + c4 * s1;
        float c5 = c4 * c1 - s4 * s1;

        float v[10] = {s1, c1, s2, c2, s3, c3, s4, c4, s5, c5};
        const uint32_t wb = hoff + r * A_STRIDE_B + fl * 20;
        #pragma unroll
        for (int p = 0; p < 5; p++) {
            float l0, l1;
            uint32_t hp = pack_hi(v[2 * p], v[2 * p + 1], l0, l1);
            uint32_t lp = pack_only(l0, l1);
            sts32(wb + p * 4, hp);
            sts32(wb + ABUF_BYTES + p * 4, lp);
        }
    }
}

// ---------------------------------------------------------------- main kernel
__global__ void __launch_bounds__(THREADS, 2)
kan_mma_kernel(const float* __restrict__ x, float* __restrict__ out, int n_rows)
{
    extern __shared__ __align__(16) unsigned char smem[];
    const uint32_t sbase = smem_u32(smem);
    const int tid  = threadIdx.x;
    const int lane = tid & 31;
    const int wid  = tid >> 5;
    const int mw   = wid & 3;    // M warp: rows mw*32
    const int nw   = wid >> 2;   // N warp: cols nw*32

    const long tile_row0 = (long)blockIdx.x * TILE_M;

    float d[2][4][4];
    #pragma unroll
    for (int mt = 0; mt < 2; mt++)
        #pragma unroll
        for (int j = 0; j < 4; j++)
            #pragma unroll
            for (int e = 0; e < 4; e++) d[mt][j][e] = 0.f;

    const int lrow = lane & 15, lcol = lane >> 4;
    const uint32_t aOff = (uint32_t)(mw * 32 + lrow) * A_STRIDE_B + lcol * 16;

    // prologue: generate chunk 0
    gen_chunk(x, smem, sbase, tile_row0, n_rows, 0, 0, tid);
    __syncthreads();

    for (int ch = 0; ch < NCHUNK; ch++) {
        const int buf = ch & 1;

        // produce next chunk into the other buffer (overlaps with MMA below)
        if (ch + 1 < NCHUNK)
            gen_chunk(x, smem, sbase, tile_row0, n_rows, ch + 1, buf ^ 1, tid);

        // === mma on current buffer: 5 k-steps x 3 terms x (2 mt x 4 nt) ===
        const uint32_t aBase = sbase + buf * BUF_STRIDE + aOff;
        #pragma unroll
        for (int s = 0; s < KSTEPS; s++) {
            uint32_t aAddr = aBase + s * 32;
            uint32_t ah[2][4], al[2][4];
            ldm4(ah[0], aAddr);
            ldm4(ah[1], aAddr + 16 * A_STRIDE_B);
            ldm4(al[0], aAddr + ABUF_BYTES);
            ldm4(al[1], aAddr + ABUF_BYTES + 16 * A_STRIDE_B);

            uint32_t bh[4][2], bl[4][2];
            const int fragIdx = ((ch * KSTEPS + s) * 8 + nw * 4);
            #pragma unroll
            for (int j = 0; j < 4; j++) {
                const int off = (fragIdx + j) * 256 + lane * 8;
                uint2 vh = __ldg((const uint2*)(g_Bh + off));
                uint2 vl = __ldg((const uint2*)(g_Bl + off));
                bh[j][0] = vh.x; bh[j][1] = vh.y;
                bl[j][0] = vl.x; bl[j][1] = vl.y;
            }

            #pragma unroll
            for (int mt = 0; mt < 2; mt++)
                #pragma unroll
                for (int j = 0; j < 4; j++) {
                    mma16816(d[mt][j], ah[mt], bh[j]);   // hi*hi
                    mma16816(d[mt][j], al[mt], bh[j]);   // lo*hi
                    mma16816(d[mt][j], ah[mt], bl[j]);   // hi*lo
                }
        }
        __syncthreads();
    }

    // ---- epilogue: add fp32 constant (ones-col + bias), store ----
    float c0v[4][2];
    #pragma unroll
    for (int j = 0; j < 4; j++) {
        const int col = nw * 32 + j * 8 + (lane & 3) * 2;
        c0v[j][0] = __ldg(&g_c0[col]);
        c0v[j][1] = __ldg(&g_c0[col + 1]);
    }
    #pragma unroll
    for (int mt = 0; mt < 2; mt++) {
        #pragma unroll
        for (int half = 0; half < 2; half++) {
            const long grow = tile_row0 + mw * 32 + mt * 16 + (lane >> 2) + half * 8;
            if (grow < n_rows) {
                #pragma unroll
                for (int j = 0; j < 4; j++) {
                    const int col = nw * 32 + j * 8 + (lane & 3) * 2;
                    float2 v;
                    v.x = d[mt][j][half * 2 + 0] + c0v[j][0];
                    v.y = d[mt][j][half * 2 + 1] + c0v[j][1];
                    *(float2*)(out + grow * HID + col) = v;
                }
            }
        }
    }
}

// ---------------------------------------------------------------- launch
extern "C" void kernel_launch(void* const* d_in, const int* in_sizes, int n_in,
                              void* d_out, int out_size)
{
    const float* x = (const float*)d_in[0];
    const float* W = (const float*)d_in[1];
    const float* b = (const float*)d_in[2];
    float* out = (float*)d_out;

    const int n_rows = in_sizes[0] / IN_DIM;    // 131072
    const int tiles = (n_rows + TILE_M - 1) / TILE_M;

    cudaFuncSetAttribute(kan_mma_kernel,
                         cudaFuncAttributeMaxDynamicSharedMemorySize, SMEM_TOTAL);

    prep_kernel<<<(KS_TOTAL * 8 * 32 + 255) / 256, 256>>>(W, b);
    kan_mma_kernel<<<tiles, THREADS, SMEM_TOTAL>>>(x, out, n_rows);
}

// round 8
// speedup vs baseline: 6.4531x; 1.1117x over previous
#include <cuda_runtime.h>
#include <cuda_bf16.h>
#include <cuda_fp16.h>
#include <cstdint>

#define IN_DIM   32
#define NB       11
#define FPAD     10                    // basis cols per feature in GEMM (sin/cos only)
#define HID      64
#define TILE_M   128
#define NCHUNK   4
#define FPC      8                     // features per chunk
#define KSTEPS   5                     // k16-steps per chunk (80 cols)
#define KS_TOTAL 20
#define THREADS  256
#define NCTAS    296                   // 148 SMs x 2 resident CTAs

#define A_STRIDE_B  176                // bytes per A row (88 halves; 80 used)

// ---- SMEM layout (bytes): double-buffered A hi/lo ----
#define ABUF_BYTES  (TILE_M * A_STRIDE_B)       // 22528
#define BUF_STRIDE  (2 * ABUF_BYTES)            // 45056 (hi+lo per buffer)
#define SMEM_TOTAL  (2 * BUF_STRIDE)            // 90112

#define BFRAG_BYTES (KS_TOTAL * 8 * 32 * 8)     // 40960

__device__ __align__(16) unsigned char g_Bh[BFRAG_BYTES];   // fp16 fragments
__device__ float g_c0[HID];            // sum_f (W[f][0][:] + b[f][:]), fp32 exact

// ---------------------------------------------------------------- helpers
__device__ __forceinline__ uint32_t smem_u32(const void* p) {
    uint32_t a;
    asm("{ .reg .u64 t; cvta.to.shared.u64 t, %1; cvt.u32.u64 %0, t; }"
        : "=r"(a) : "l"(p));
    return a;
}
__device__ __forceinline__ void ldm4(uint32_t* r, uint32_t a) {
    asm volatile("ldmatrix.sync.aligned.m8n8.x4.shared.b16 {%0,%1,%2,%3}, [%4];"
                 : "=r"(r[0]), "=r"(r[1]), "=r"(r[2]), "=r"(r[3]) : "r"(a));
}
__device__ __forceinline__ void sts32(uint32_t a, uint32_t v) {
    asm volatile("st.shared.b32 [%0], %1;" :: "r"(a), "r"(v) : "memory");
}
__device__ __forceinline__ void mma16816(float* d, const uint32_t* a, const uint32_t* b) {
    asm volatile(
        "mma.sync.aligned.m16n8k16.row.col.f32.f16.f16.f32 "
        "{%0,%1,%2,%3}, {%4,%5,%6,%7}, {%8,%9}, {%0,%1,%2,%3};"
        : "+f"(d[0]), "+f"(d[1]), "+f"(d[2]), "+f"(d[3])
        : "r"(a[0]), "r"(a[1]), "r"(a[2]), "r"(a[3]), "r"(b[0]), "r"(b[1]));
}

// ---------------------------------------------------------------- prep kernel
// B[k][n], k = f*10 + c (c -> basis col c+1 = sin1,cos1,...,sin5,cos5) as fp16
// in mma B-fragment layout. Also g_c0 = sum_f(W[f][0]+b[f]).
__global__ void prep_kernel(const float* __restrict__ W, const float* __restrict__ bias) {
    int idx = blockIdx.x * blockDim.x + threadIdx.x;
    if (idx < HID) {
        float s = 0.f;
        #pragma unroll
        for (int f = 0; f < IN_DIM; f++)
            s += W[(f * NB) * HID + idx] + bias[f * HID + idx];
        g_c0[idx] = s;
    }
    if (idx >= KS_TOTAL * 8 * 32) return;
    int t   = idx & 31;
    int nt  = (idx >> 5) & 7;
    int ksg = idx >> 8;
    int n     = nt * 8 + (t >> 2);
    int kbase = ksg * 16 + (t & 3) * 2;

    uint32_t hi[2];
    #pragma unroll
    for (int half = 0; half < 2; half++) {
        int k0 = kbase + half * 8;
        float v0 = W[((k0 / FPAD) * NB + (k0 % FPAD) + 1) * HID + n];
        int k1 = k0 + 1;
        float v1 = W[((k1 / FPAD) * NB + (k1 % FPAD) + 1) * HID + n];
        __half2 h2 = __floats2half2_rn(v0, v1);
        hi[half] = *(uint32_t*)&h2;
    }
    *(uint2*)(g_Bh + idx * 8) = make_uint2(hi[0], hi[1]);
}

// ---------------------------------------------------------------- A generation
__device__ __forceinline__ void gen_chunk(const float* __restrict__ x,
                                          uint32_t sbase, long row0, int n_rows,
                                          int ch, int buf, int tid)
{
    const uint32_t hoff = sbase + buf * BUF_STRIDE;
    #pragma unroll
    for (int i = 0; i < 4; i++) {
        const int job = tid + THREADS * i;     // 0..1023
        const int r   = job >> 3;
        const int fl  = job & 7;
        const long grow = row0 + r;
        const int f = ch * FPC + fl;
        float xv = (grow < n_rows) ? __ldg(x + grow * IN_DIM + f) : 0.f;

        // range reduce by pi, Taylor sin/cos (FMA-only)
        float t  = fmaf(xv, 0.3183098861837907f, 12582912.0f);
        uint32_t ti = __float_as_uint(t);
        float nf = t - 12582912.0f;
        float rr = fmaf(nf, -3.14159274101257324f, xv);
        rr = fmaf(nf, 8.74227800037247e-8f, rr);
        float sgn = (ti & 1u) ? -1.0f : 1.0f;

        float r2 = rr * rr;
        float sp = -2.50521083854e-8f;
        sp = fmaf(sp, r2, 2.75573192240e-6f);
        sp = fmaf(sp, r2, -1.98412698413e-4f);
        sp = fmaf(sp, r2, 8.33333333333e-3f);
        sp = fmaf(sp, r2, -1.66666666667e-1f);
        float s1 = fmaf(sp * r2, rr, rr);
        float cp = 2.08767569879e-9f;
        cp = fmaf(cp, r2, -2.75573192240e-7f);
        cp = fmaf(cp, r2, 2.48015873016e-5f);
        cp = fmaf(cp, r2, -1.38888888889e-3f);
        cp = fmaf(cp, r2, 4.16666666667e-2f);
        cp = fmaf(cp, r2, -0.5f);
        float c1 = fmaf(cp, r2, 1.0f);
        s1 *= sgn; c1 *= sgn;

        float s2 = 2.f * s1 * c1;
        float c2 = fmaf(c1, c1, -(s1 * s1));
        float s3 = s2 * c1 + c2 * s1;
        float c3 = c2 * c1 - s2 * s1;
        float s4 = s3 * c1 + c3 * s1;
        float c4 = c3 * c1 - s3 * s1;
        float s5 = s4 * c1 + c4 * s1;
        float c5 = c4 * c1 - s4 * s1;

        float v[10] = {s1, c1, s2, c2, s3, c3, s4, c4, s5, c5};
        const uint32_t wb = hoff + r * A_STRIDE_B + fl * 20;
        #pragma unroll
        for (int p = 0; p < 5; p++) {
            float v0 = v[2 * p], v1 = v[2 * p + 1];
            __half2 h2 = __floats2half2_rn(v0, v1);
            float2 bk = __half22float2(h2);
            __half2 l2 = __floats2half2_rn(v0 - bk.x, v1 - bk.y);
            sts32(wb + p * 4, *(uint32_t*)&h2);
            sts32(wb + ABUF_BYTES + p * 4, *(uint32_t*)&l2);
        }
    }
}

// ---------------------------------------------------------------- main kernel
__global__ void __launch_bounds__(THREADS, 2)
kan_mma_kernel(const float* __restrict__ x, float* __restrict__ out,
               int n_rows, int ntiles)
{
    extern __shared__ __align__(16) unsigned char smem[];
    const uint32_t sbase = smem_u32(smem);
    const int tid  = threadIdx.x;
    const int lane = tid & 31;
    const int wid  = tid >> 5;
    const int mw   = wid & 3;    // M warp: rows mw*32
    const int nw   = wid >> 2;   // N warp: cols nw*32

    const int lrow = lane & 15, lcol = lane >> 4;
    const uint32_t aOff = (uint32_t)(mw * 32 + lrow) * A_STRIDE_B + lcol * 16;

    // epilogue constant (ones-col + bias), fp32 exact
    float c0v[4][2];
    #pragma unroll
    for (int j = 0; j < 4; j++) {
        const int col = nw * 32 + j * 8 + (lane & 3) * 2;
        c0v[j][0] = __ldg(&g_c0[col]);
        c0v[j][1] = __ldg(&g_c0[col + 1]);
    }

    int buf = 0;
    // prologue: generate chunk 0 of first tile
    if (blockIdx.x < (unsigned)ntiles)
        gen_chunk(x, sbase, (long)blockIdx.x * TILE_M, n_rows, 0, 0, tid);
    __syncthreads();

    for (int tile = blockIdx.x; tile < ntiles; tile += gridDim.x) {
        const long tile_row0 = (long)tile * TILE_M;

        float d[2][4][4];
        #pragma unroll
        for (int mt = 0; mt < 2; mt++)
            #pragma unroll
            for (int j = 0; j < 4; j++)
                #pragma unroll
                for (int e = 0; e < 4; e++) d[mt][j][e] = 0.f;

        for (int ch = 0; ch < NCHUNK; ch++) {
            // produce next chunk (next tile's chunk 0 when wrapping)
            const int  ntile = (ch < NCHUNK - 1) ? tile : tile + gridDim.x;
            const int  nch   = (ch < NCHUNK - 1) ? ch + 1 : 0;
            if (ntile < ntiles)
                gen_chunk(x, sbase, (long)ntile * TILE_M, n_rows, nch, buf ^ 1, tid);

            // === mma on current buffer: 5 k-steps x 2 terms x (2 mt x 4 nt) ===
            const uint32_t aBase = sbase + buf * BUF_STRIDE + aOff;
            #pragma unroll
            for (int s = 0; s < KSTEPS; s++) {
                uint32_t aAddr = aBase + s * 32;
                uint32_t ah[2][4], al[2][4];
                ldm4(ah[0], aAddr);
                ldm4(ah[1], aAddr + 16 * A_STRIDE_B);
                ldm4(al[0], aAddr + ABUF_BYTES);
                ldm4(al[1], aAddr + ABUF_BYTES + 16 * A_STRIDE_B);

                uint32_t bh[4][2];
                const int fragIdx = ((ch * KSTEPS + s) * 8 + nw * 4);
                #pragma unroll
                for (int j = 0; j < 4; j++) {
                    uint2 vh = __ldg((const uint2*)(g_Bh + (fragIdx + j) * 256 + lane * 8));
                    bh[j][0] = vh.x; bh[j][1] = vh.y;
                }

                #pragma unroll
                for (int mt = 0; mt < 2; mt++)
                    #pragma unroll
                    for (int j = 0; j < 4; j++) {
                        mma16816(d[mt][j], ah[mt], bh[j]);   // hi*B
                        mma16816(d[mt][j], al[mt], bh[j]);   // lo*B (A residual)
                    }
            }
            __syncthreads();
            buf ^= 1;
        }

        // ---- epilogue: add fp32 constant, store ----
        #pragma unroll
        for (int mt = 0; mt < 2; mt++) {
            #pragma unroll
            for (int half = 0; half < 2; half++) {
                const long grow = tile_row0 + mw * 32 + mt * 16 + (lane >> 2) + half * 8;
                if (grow < n_rows) {
                    #pragma unroll
                    for (int j = 0; j < 4; j++) {
                        const int col = nw * 32 + j * 8 + (lane & 3) * 2;
                        float2 v;
                        v.x = d[mt][j][half * 2 + 0] + c0v[j][0];
                        v.y = d[mt][j][half * 2 + 1] + c0v[j][1];
                        *(float2*)(out + grow * HID + col) = v;
                    }
                }
            }
        }
    }
}

// ---------------------------------------------------------------- launch
extern "C" void kernel_launch(void* const* d_in, const int* in_sizes, int n_in,
                              void* d_out, int out_size)
{
    const float* x = (const float*)d_in[0];
    const float* W = (const float*)d_in[1];
    const float* b = (const float*)d_in[2];
    float* out = (float*)d_out;

    const int n_rows = in_sizes[0] / IN_DIM;    // 131072
    const int ntiles = (n_rows + TILE_M - 1) / TILE_M;
    const int grid = ntiles < NCTAS ? ntiles : NCTAS;

    cudaFuncSetAttribute(kan_mma_kernel,
                         cudaFuncAttributeMaxDynamicSharedMemorySize, SMEM_TOTAL);

    prep_kernel<<<(KS_TOTAL * 8 * 32 + 255) / 256, 256>>>(W, b);
    kan_mma_kernel<<<grid, THREADS, SMEM_TOTAL>>>(x, out, n_rows, ntiles);
}

// round 9
// speedup vs baseline: 9.1252x; 1.4141x over previous
#include <cuda_runtime.h>
#include <cuda_bf16.h>
#include <cuda_fp16.h>
#include <cstdint>

#define IN_DIM   32
#define NB       11
#define FPAD     10                    // basis cols per feature in GEMM (sin/cos only)
#define HID      64
#define TILE_M   128
#define NCHUNK   4
#define FPC      8                     // features per chunk
#define KSTEPS   5                     // k16-steps per chunk (80 cols)
#define KS_TOTAL 20
#define THREADS  256
#define NCTAS    296                   // 148 SMs x 2 resident CTAs

#define A_STRIDE_B  176                // bytes per A row (88 halves; 80 used)

// ---- SMEM layout (bytes): double-buffered A (fp16, single image) ----
#define ABUF_BYTES  (TILE_M * A_STRIDE_B)       // 22528
#define SMEM_TOTAL  (2 * ABUF_BYTES)            // 45056

#define BFRAG_BYTES (KS_TOTAL * 8 * 32 * 8)     // 40960

__device__ __align__(16) unsigned char g_Bh[BFRAG_BYTES];   // fp16 fragments
__device__ float g_c0[HID];            // sum_f (W[f][0][:] + b[f][:]), fp32 exact

// ---------------------------------------------------------------- helpers
__device__ __forceinline__ uint32_t smem_u32(const void* p) {
    uint32_t a;
    asm("{ .reg .u64 t; cvta.to.shared.u64 t, %1; cvt.u32.u64 %0, t; }"
        : "=r"(a) : "l"(p));
    return a;
}
__device__ __forceinline__ void ldm4(uint32_t* r, uint32_t a) {
    asm volatile("ldmatrix.sync.aligned.m8n8.x4.shared.b16 {%0,%1,%2,%3}, [%4];"
                 : "=r"(r[0]), "=r"(r[1]), "=r"(r[2]), "=r"(r[3]) : "r"(a));
}
__device__ __forceinline__ void sts32(uint32_t a, uint32_t v) {
    asm volatile("st.shared.b32 [%0], %1;" :: "r"(a), "r"(v) : "memory");
}
__device__ __forceinline__ void mma16816(float* d, const uint32_t* a, const uint32_t* b) {
    asm volatile(
        "mma.sync.aligned.m16n8k16.row.col.f32.f16.f16.f32 "
        "{%0,%1,%2,%3}, {%4,%5,%6,%7}, {%8,%9}, {%0,%1,%2,%3};"
        : "+f"(d[0]), "+f"(d[1]), "+f"(d[2]), "+f"(d[3])
        : "r"(a[0]), "r"(a[1]), "r"(a[2]), "r"(a[3]), "r"(b[0]), "r"(b[1]));
}

// ---------------------------------------------------------------- prep kernel
// B[k][n], k = f*10 + c (c -> basis col c+1 = sin1,cos1,...,sin5,cos5) as fp16
// in mma B-fragment layout. Also g_c0 = sum_f(W[f][0]+b[f]).
__global__ void prep_kernel(const float* __restrict__ W, const float* __restrict__ bias) {
    int idx = blockIdx.x * blockDim.x + threadIdx.x;
    if (idx < HID) {
        float s = 0.f;
        #pragma unroll
        for (int f = 0; f < IN_DIM; f++)
            s += W[(f * NB) * HID + idx] + bias[f * HID + idx];
        g_c0[idx] = s;
    }
    if (idx >= KS_TOTAL * 8 * 32) return;
    int t   = idx & 31;
    int nt  = (idx >> 5) & 7;
    int ksg = idx >> 8;
    int n     = nt * 8 + (t >> 2);
    int kbase = ksg * 16 + (t & 3) * 2;

    uint32_t hi[2];
    #pragma unroll
    for (int half = 0; half < 2; half++) {
        int k0 = kbase + half * 8;
        float v0 = W[((k0 / FPAD) * NB + (k0 % FPAD) + 1) * HID + n];
        int k1 = k0 + 1;
        float v1 = W[((k1 / FPAD) * NB + (k1 % FPAD) + 1) * HID + n];
        __half2 h2 = __floats2half2_rn(v0, v1);
        hi[half] = *(uint32_t*)&h2;
    }
    *(uint2*)(g_Bh + idx * 8) = make_uint2(hi[0], hi[1]);
}

// ---------------------------------------------------------------- A generation
__device__ __forceinline__ void gen_chunk(const float* __restrict__ x,
                                          uint32_t sbase, long row0, int n_rows,
                                          int ch, int buf, int tid)
{
    const uint32_t hoff = sbase + buf * ABUF_BYTES;
    #pragma unroll
    for (int i = 0; i < 4; i++) {
        const int job = tid + THREADS * i;     // 0..1023
        const int r   = job >> 3;
        const int fl  = job & 7;
        const long grow = row0 + r;
        const int f = ch * FPC + fl;
        float xv = (grow < n_rows) ? __ldg(x + grow * IN_DIM + f) : 0.f;

        // range reduce by pi, Taylor sin/cos (FMA-only)
        float t  = fmaf(xv, 0.3183098861837907f, 12582912.0f);
        uint32_t ti = __float_as_uint(t);
        float nf = t - 12582912.0f;
        float rr = fmaf(nf, -3.14159274101257324f, xv);
        rr = fmaf(nf, 8.74227800037247e-8f, rr);
        float sgn = (ti & 1u) ? -1.0f : 1.0f;

        float r2 = rr * rr;
        float sp = -2.50521083854e-8f;
        sp = fmaf(sp, r2, 2.75573192240e-6f);
        sp = fmaf(sp, r2, -1.98412698413e-4f);
        sp = fmaf(sp, r2, 8.33333333333e-3f);
        sp = fmaf(sp, r2, -1.66666666667e-1f);
        float s1 = fmaf(sp * r2, rr, rr);
        float cp = 2.08767569879e-9f;
        cp = fmaf(cp, r2, -2.75573192240e-7f);
        cp = fmaf(cp, r2, 2.48015873016e-5f);
        cp = fmaf(cp, r2, -1.38888888889e-3f);
        cp = fmaf(cp, r2, 4.16666666667e-2f);
        cp = fmaf(cp, r2, -0.5f);
        float c1 = fmaf(cp, r2, 1.0f);
        s1 *= sgn; c1 *= sgn;

        float s2 = 2.f * s1 * c1;
        float c2 = fmaf(c1, c1, -(s1 * s1));
        float s3 = s2 * c1 + c2 * s1;
        float c3 = c2 * c1 - s2 * s1;
        float s4 = s3 * c1 + c3 * s1;
        float c4 = c3 * c1 - s3 * s1;
        float s5 = s4 * c1 + c4 * s1;
        float c5 = c4 * c1 - s4 * s1;

        float v[10] = {s1, c1, s2, c2, s3, c3, s4, c4, s5, c5};
        const uint32_t wb = hoff + r * A_STRIDE_B + fl * 20;
        #pragma unroll
        for (int p = 0; p < 5; p++) {
            __half2 h2 = __floats2half2_rn(v[2 * p], v[2 * p + 1]);
            sts32(wb + p * 4, *(uint32_t*)&h2);
        }
    }
}

// ---------------------------------------------------------------- main kernel
__global__ void __launch_bounds__(THREADS, 2)
kan_mma_kernel(const float* __restrict__ x, float* __restrict__ out,
               int n_rows, int ntiles)
{
    extern __shared__ __align__(16) unsigned char smem[];
    const uint32_t sbase = smem_u32(smem);
    const int tid  = threadIdx.x;
    const int lane = tid & 31;
    const int wid  = tid >> 5;
    const int mw   = wid & 3;    // M warp: rows mw*32
    const int nw   = wid >> 2;   // N warp: cols nw*32

    const int lrow = lane & 15, lcol = lane >> 4;
    const uint32_t aOff = (uint32_t)(mw * 32 + lrow) * A_STRIDE_B + lcol * 16;

    // epilogue constant (ones-col + bias), fp32 exact
    float c0v[4][2];
    #pragma unroll
    for (int j = 0; j < 4; j++) {
        const int col = nw * 32 + j * 8 + (lane & 3) * 2;
        c0v[j][0] = __ldg(&g_c0[col]);
        c0v[j][1] = __ldg(&g_c0[col + 1]);
    }

    int buf = 0;
    // prologue: generate chunk 0 of first tile
    if (blockIdx.x < (unsigned)ntiles)
        gen_chunk(x, sbase, (long)blockIdx.x * TILE_M, n_rows, 0, 0, tid);
    __syncthreads();

    for (int tile = blockIdx.x; tile < ntiles; tile += gridDim.x) {
        const long tile_row0 = (long)tile * TILE_M;

        float d[2][4][4];
        #pragma unroll
        for (int mt = 0; mt < 2; mt++)
            #pragma unroll
            for (int j = 0; j < 4; j++)
                #pragma unroll
                for (int e = 0; e < 4; e++) d[mt][j][e] = 0.f;

        for (int ch = 0; ch < NCHUNK; ch++) {
            // produce next chunk (next tile's chunk 0 when wrapping)
            const int  ntile = (ch < NCHUNK - 1) ? tile : tile + gridDim.x;
            const int  nch   = (ch < NCHUNK - 1) ? ch + 1 : 0;
            if (ntile < ntiles)
                gen_chunk(x, sbase, (long)ntile * TILE_M, n_rows, nch, buf ^ 1, tid);

            // === mma on current buffer: 5 k-steps x (2 mt x 4 nt) ===
            const uint32_t aBase = sbase + buf * ABUF_BYTES + aOff;
            #pragma unroll
            for (int s = 0; s < KSTEPS; s++) {
                uint32_t aAddr = aBase + s * 32;
                uint32_t ah[2][4];
                ldm4(ah[0], aAddr);
                ldm4(ah[1], aAddr + 16 * A_STRIDE_B);

                uint32_t bh[4][2];
                const int fragIdx = ((ch * KSTEPS + s) * 8 + nw * 4);
                #pragma unroll
                for (int j = 0; j < 4; j++) {
                    uint2 vh = __ldg((const uint2*)(g_Bh + (fragIdx + j) * 256 + lane * 8));
                    bh[j][0] = vh.x; bh[j][1] = vh.y;
                }

                #pragma unroll
                for (int mt = 0; mt < 2; mt++)
                    #pragma unroll
                    for (int j = 0; j < 4; j++)
                        mma16816(d[mt][j], ah[mt], bh[j]);
            }
            __syncthreads();
            buf ^= 1;
        }

        // ---- epilogue: add fp32 constant, store ----
        #pragma unroll
        for (int mt = 0; mt < 2; mt++) {
            #pragma unroll
            for (int half = 0; half < 2; half++) {
                const long grow = tile_row0 + mw * 32 + mt * 16 + (lane >> 2) + half * 8;
                if (grow < n_rows) {
                    #pragma unroll
                    for (int j = 0; j < 4; j++) {
                        const int col = nw * 32 + j * 8 + (lane & 3) * 2;
                        float2 v;
                        v.x = d[mt][j][half * 2 + 0] + c0v[j][0];
                        v.y = d[mt][j][half * 2 + 1] + c0v[j][1];
                        *(float2*)(out + grow * HID + col) = v;
                    }
                }
            }
        }
    }
}

// ---------------------------------------------------------------- launch
extern "C" void kernel_launch(void* const* d_in, const int* in_sizes, int n_in,
                              void* d_out, int out_size)
{
    const float* x = (const float*)d_in[0];
    const float* W = (const float*)d_in[1];
    const float* b = (const float*)d_in[2];
    float* out = (float*)d_out;

    const int n_rows = in_sizes[0] / IN_DIM;    // 131072
    const int ntiles = (n_rows + TILE_M - 1) / TILE_M;
    const int grid = ntiles < NCTAS ? ntiles : NCTAS;

    cudaFuncSetAttribute(kan_mma_kernel,
                         cudaFuncAttributeMaxDynamicSharedMemorySize, SMEM_TOTAL);

    prep_kernel<<<(KS_TOTAL * 8 * 32 + 255) / 256, 256>>>(W, b);
    kan_mma_kernel<<<grid, THREADS, SMEM_TOTAL>>>(x, out, n_rows, ntiles);
}

// round 10
// speedup vs baseline: 9.6462x; 1.0571x over previous
#include <cuda_runtime.h>
#include <cuda_bf16.h>
#include <cuda_fp16.h>
#include <cstdint>

#define IN_DIM   32
#define NB       11
#define FPAD     10                    // basis cols per feature in GEMM (sin/cos only)
#define HID      64
#define TILE_M   128
#define NCHUNK   2
#define FPC      16                    // features per chunk
#define KSTEPS   10                    // k16-steps per chunk (160 cols)
#define KS_TOTAL 20
#define THREADS  256
#define NCTAS    296                   // 148 SMs x 2 resident CTAs

#define A_STRIDE_B  336                // bytes per A row (168 halves; 160 used), 21*16

// ---- SMEM layout (bytes): double-buffered A (fp16) ----
#define ABUF_BYTES  (TILE_M * A_STRIDE_B)       // 43008
#define SMEM_TOTAL  (2 * ABUF_BYTES)            // 86016

#define BFRAG_BYTES (KS_TOTAL * 8 * 32 * 8)     // 40960

__device__ __align__(16) unsigned char g_Bh[BFRAG_BYTES];   // fp16 fragments
__device__ float g_c0[HID];            // sum_f (W[f][0][:] + b[f][:]), fp32 exact

// ---------------------------------------------------------------- helpers
__device__ __forceinline__ uint32_t smem_u32(const void* p) {
    uint32_t a;
    asm("{ .reg .u64 t; cvta.to.shared.u64 t, %1; cvt.u32.u64 %0, t; }"
        : "=r"(a) : "l"(p));
    return a;
}
__device__ __forceinline__ void ldm4(uint32_t* r, uint32_t a) {
    asm volatile("ldmatrix.sync.aligned.m8n8.x4.shared.b16 {%0,%1,%2,%3}, [%4];"
                 : "=r"(r[0]), "=r"(r[1]), "=r"(r[2]), "=r"(r[3]) : "r"(a));
}
__device__ __forceinline__ void sts64(uint32_t a, uint32_t v0, uint32_t v1) {
    asm volatile("st.shared.v2.b32 [%0], {%1, %2};" :: "r"(a), "r"(v0), "r"(v1) : "memory");
}
__device__ __forceinline__ void mma16816(float* d, const uint32_t* a, const uint32_t* b) {
    asm volatile(
        "mma.sync.aligned.m16n8k16.row.col.f32.f16.f16.f32 "
        "{%0,%1,%2,%3}, {%4,%5,%6,%7}, {%8,%9}, {%0,%1,%2,%3};"
        : "+f"(d[0]), "+f"(d[1]), "+f"(d[2]), "+f"(d[3])
        : "r"(a[0]), "r"(a[1]), "r"(a[2]), "r"(a[3]), "r"(b[0]), "r"(b[1]));
}

// sin/cos harmonics 1..5 of xv -> v[10] = {s1,c1,s2,c2,...,s5,c5}
__device__ __forceinline__ void sincos_harm(float xv, float* v) {
    float t  = fmaf(xv, 0.3183098861837907f, 12582912.0f);
    uint32_t ti = __float_as_uint(t);
    float nf = t - 12582912.0f;
    float rr = fmaf(nf, -3.14159274101257324f, xv);
    rr = fmaf(nf, 8.74227800037247e-8f, rr);
    float sgn = (ti & 1u) ? -1.0f : 1.0f;

    float r2 = rr * rr;
    float sp = -2.50521083854e-8f;
    sp = fmaf(sp, r2, 2.75573192240e-6f);
    sp = fmaf(sp, r2, -1.98412698413e-4f);
    sp = fmaf(sp, r2, 8.33333333333e-3f);
    sp = fmaf(sp, r2, -1.66666666667e-1f);
    float s1 = fmaf(sp * r2, rr, rr);
    float cp = 2.08767569879e-9f;
    cp = fmaf(cp, r2, -2.75573192240e-7f);
    cp = fmaf(cp, r2, 2.48015873016e-5f);
    cp = fmaf(cp, r2, -1.38888888889e-3f);
    cp = fmaf(cp, r2, 4.16666666667e-2f);
    cp = fmaf(cp, r2, -0.5f);
    float c1 = fmaf(cp, r2, 1.0f);
    s1 *= sgn; c1 *= sgn;

    float s2 = 2.f * s1 * c1;
    float c2 = fmaf(c1, c1, -(s1 * s1));
    float s3 = s2 * c1 + c2 * s1;
    float c3 = c2 * c1 - s2 * s1;
    float s4 = s3 * c1 + c3 * s1;
    float c4 = c3 * c1 - s3 * s1;
    float s5 = s4 * c1 + c4 * s1;
    float c5 = c4 * c1 - s4 * s1;
    v[0] = s1; v[1] = c1; v[2] = s2; v[3] = c2; v[4] = s3;
    v[5] = c3; v[6] = s4; v[7] = c4; v[8] = s5; v[9] = c5;
}

// ---------------------------------------------------------------- prep kernel
// B[k][n], k = f*10 + c (c -> basis col c+1) as fp16 in mma B-fragment layout.
// Also g_c0 = sum_f(W[f][0]+b[f]).
__global__ void prep_kernel(const float* __restrict__ W, const float* __restrict__ bias) {
    int idx = blockIdx.x * blockDim.x + threadIdx.x;
    if (idx < HID) {
        float s = 0.f;
        #pragma unroll
        for (int f = 0; f < IN_DIM; f++)
            s += W[(f * NB) * HID + idx] + bias[f * HID + idx];
        g_c0[idx] = s;
    }
    if (idx >= KS_TOTAL * 8 * 32) return;
    int t   = idx & 31;
    int nt  = (idx >> 5) & 7;
    int ksg = idx >> 8;
    int n     = nt * 8 + (t >> 2);
    int kbase = ksg * 16 + (t & 3) * 2;

    uint32_t hi[2];
    #pragma unroll
    for (int half = 0; half < 2; half++) {
        int k0 = kbase + half * 8;
        float v0 = W[((k0 / FPAD) * NB + (k0 % FPAD) + 1) * HID + n];
        int k1 = k0 + 1;
        float v1 = W[((k1 / FPAD) * NB + (k1 % FPAD) + 1) * HID + n];
        __half2 h2 = __floats2half2_rn(v0, v1);
        hi[half] = *(uint32_t*)&h2;
    }
    *(uint2*)(g_Bh + idx * 8) = make_uint2(hi[0], hi[1]);
}

// ---------------------------------------------------------------- A generation
// 1024 jobs: 128 rows x 8 feature-pairs; each job does 2 sincos + 5 STS.64
__device__ __forceinline__ void gen_chunk(const float* __restrict__ x,
                                          uint32_t sbase, long row0, int n_rows,
                                          int ch, int buf, int tid)
{
    const uint32_t hoff = sbase + buf * ABUF_BYTES;
    #pragma unroll
    for (int i = 0; i < 4; i++) {
        const int job = tid + THREADS * i;     // 0..1023
        const int r   = job >> 3;
        const int fp  = job & 7;
        const long grow = row0 + r;
        const int f0 = ch * FPC + fp * 2;

        float2 xv2 = make_float2(0.f, 0.f);
        if (grow < n_rows)
            xv2 = __ldg((const float2*)(x + grow * IN_DIM + f0));

        float v[20];
        sincos_harm(xv2.x, v);
        sincos_harm(xv2.y, v + 10);

        const uint32_t wb = hoff + r * A_STRIDE_B + fp * 40;
        #pragma unroll
        for (int p = 0; p < 5; p++) {
            __half2 a = __floats2half2_rn(v[4 * p + 0], v[4 * p + 1]);
            __half2 b = __floats2half2_rn(v[4 * p + 2], v[4 * p + 3]);
            sts64(wb + p * 8, *(uint32_t*)&a, *(uint32_t*)&b);
        }
    }
}

// ---------------------------------------------------------------- main kernel
__global__ void __launch_bounds__(THREADS, 2)
kan_mma_kernel(const float* __restrict__ x, float* __restrict__ out,
               int n_rows, int ntiles)
{
    extern __shared__ __align__(16) unsigned char smem[];
    const uint32_t sbase = smem_u32(smem);
    const int tid  = threadIdx.x;
    const int lane = tid & 31;
    const int wid  = tid >> 5;
    const int mw   = wid & 3;    // M warp: rows mw*32
    const int nw   = wid >> 2;   // N warp: cols nw*32

    const int lrow = lane & 15, lcol = lane >> 4;
    const uint32_t aOff = (uint32_t)(mw * 32 + lrow) * A_STRIDE_B + lcol * 16;

    // epilogue constant (ones-col + bias), fp32 exact
    float c0v[4][2];
    #pragma unroll
    for (int j = 0; j < 4; j++) {
        const int col = nw * 32 + j * 8 + (lane & 3) * 2;
        c0v[j][0] = __ldg(&g_c0[col]);
        c0v[j][1] = __ldg(&g_c0[col + 1]);
    }

    int buf = 0;
    if (blockIdx.x < (unsigned)ntiles)
        gen_chunk(x, sbase, (long)blockIdx.x * TILE_M, n_rows, 0, 0, tid);
    __syncthreads();

    for (int tile = blockIdx.x; tile < ntiles; tile += gridDim.x) {
        const long tile_row0 = (long)tile * TILE_M;

        float d[2][4][4];
        #pragma unroll
        for (int mt = 0; mt < 2; mt++)
            #pragma unroll
            for (int j = 0; j < 4; j++)
                #pragma unroll
                for (int e = 0; e < 4; e++) d[mt][j][e] = 0.f;

        for (int ch = 0; ch < NCHUNK; ch++) {
            // produce next chunk (next tile's chunk 0 when wrapping)
            const int  ntile = (ch < NCHUNK - 1) ? tile : tile + gridDim.x;
            const int  nch   = (ch < NCHUNK - 1) ? ch + 1 : 0;
            if (ntile < ntiles)
                gen_chunk(x, sbase, (long)ntile * TILE_M, n_rows, nch, buf ^ 1, tid);

            // === mma on current buffer: 10 k-steps x (2 mt x 4 nt) ===
            const uint32_t aBase = sbase + buf * ABUF_BYTES + aOff;
            #pragma unroll
            for (int s = 0; s < KSTEPS; s++) {
                uint32_t aAddr = aBase + s * 32;
                uint32_t ah[2][4];
                ldm4(ah[0], aAddr);
                ldm4(ah[1], aAddr + 16 * A_STRIDE_B);

                uint32_t bh[4][2];
                const int fragIdx = ((ch * KSTEPS + s) * 8 + nw * 4);
                #pragma unroll
                for (int j = 0; j < 4; j++) {
                    uint2 vh = __ldg((const uint2*)(g_Bh + (fragIdx + j) * 256 + lane * 8));
                    bh[j][0] = vh.x; bh[j][1] = vh.y;
                }

                #pragma unroll
                for (int mt = 0; mt < 2; mt++)
                    #pragma unroll
                    for (int j = 0; j < 4; j++)
                        mma16816(d[mt][j], ah[mt], bh[j]);
            }
            __syncthreads();
            buf ^= 1;
        }

        // ---- epilogue: add fp32 constant, store ----
        #pragma unroll
        for (int mt = 0; mt < 2; mt++) {
            #pragma unroll
            for (int half = 0; half < 2; half++) {
                const long grow = tile_row0 + mw * 32 + mt * 16 + (lane >> 2) + half * 8;
                if (grow < n_rows) {
                    #pragma unroll
                    for (int j = 0; j < 4; j++) {
                        const int col = nw * 32 + j * 8 + (lane & 3) * 2;
                        float2 v;
                        v.x = d[mt][j][half * 2 + 0] + c0v[j][0];
                        v.y = d[mt][j][half * 2 + 1] + c0v[j][1];
                        *(float2*)(out + grow * HID + col) = v;
                    }
                }
            }
        }
    }
}

// ---------------------------------------------------------------- launch
extern "C" void kernel_launch(void* const* d_in, const int* in_sizes, int n_in,
                              void* d_out, int out_size)
{
    const float* x = (const float*)d_in[0];
    const float* W = (const float*)d_in[1];
    const float* b = (const float*)d_in[2];
    float* out = (float*)d_out;

    const int n_rows = in_sizes[0] / IN_DIM;    // 131072
    const int ntiles = (n_rows + TILE_M - 1) / TILE_M;
    const int grid = ntiles < NCTAS ? ntiles : NCTAS;

    cudaFuncSetAttribute(kan_mma_kernel,
                         cudaFuncAttributeMaxDynamicSharedMemorySize, SMEM_TOTAL);

    prep_kernel<<<(KS_TOTAL * 8 * 32 + 255) / 256, 256>>>(W, b);
    kan_mma_kernel<<<grid, THREADS, SMEM_TOTAL>>>(x, out, n_rows, ntiles);
}